// round 2
// baseline (speedup 1.0000x reference)
#include <cuda_runtime.h>

#define TOTD 512
#define HIDD 256
#define OUTD 128

// Scratch: per-(k,half) partial sum-of-squares and partial product.
__device__ float g_sum[512];
__device__ float g_prod[512];

__global__ void __launch_bounds__(256, 8) wavelet_main_kernel(
    const float* __restrict__ h, const float* __restrict__ y, const float* __restrict__ u,
    const float* __restrict__ W1, const float* __restrict__ b1,
    const float* __restrict__ W2, const float* __restrict__ b2,
    const float* __restrict__ Wy, const float* __restrict__ by,
    float* __restrict__ out)
{
    __shared__ float4 s_inp[TOTD / 4];
    __shared__ float s_ws[8], s_wp[8];

    const int tid = threadIdx.x;
    // Build inp = concat(h[256], y[128], u[128]) in shared.
    float* si = (float*)s_inp;
    for (int i = tid; i < TOTD; i += 256) {
        float v;
        if (i < HIDD)            v = h[i];
        else if (i < HIDD + OUTD) v = y[i - HIDD];
        else                     v = u[i - HIDD - OUTD];
        si[i] = v;
    }
    __syncthreads();

    const int lane = tid & 31;
    const int w    = tid >> 5;   // warp id 0..7
    const int bx   = blockIdx.x;

    // Preload inp slice for this lane into registers (reused across all rows).
    float4 iv0 = s_inp[lane +  0];
    float4 iv1 = s_inp[lane + 32];
    float4 iv2 = s_inp[lane + 64];
    float4 iv3 = s_inp[lane + 96];

    if (bx < 512) {
        // Hidden-unit matvecs: block bx handles k = bx/2, rows [ (bx&1)*256, +256 )
        const int kk   = bx >> 1;      // 0..255
        const int half = bx & 1;
        const float* W;
        const float* b;
        if (kk == 0) { W = W1; b = b1; }
        else {
            W = W2 + (size_t)(kk - 1) * TOTD * TOTD;
            b = b2 + (size_t)(kk - 1) * TOTD;
        }

        float runs = 0.0f;   // sum of x^2
        float runp = 1.0f;   // product of (1 - x^2)
        const int rbase = half * 256 + w * 32;

        #pragma unroll 1
        for (int i = 0; i < 32; i++) {
            const int row = rbase + i;
            const float4* Wr = (const float4*)(W + (size_t)row * TOTD);
            float4 w0 = __ldcs(Wr + lane +  0);
            float4 w1 = __ldcs(Wr + lane + 32);
            float4 w2 = __ldcs(Wr + lane + 64);
            float4 w3 = __ldcs(Wr + lane + 96);
            float acc = w0.x*iv0.x + w0.y*iv0.y + w0.z*iv0.z + w0.w*iv0.w;
            acc      += w1.x*iv1.x + w1.y*iv1.y + w1.z*iv1.z + w1.w*iv1.w;
            acc      += w2.x*iv2.x + w2.y*iv2.y + w2.z*iv2.z + w2.w*iv2.w;
            acc      += w3.x*iv3.x + w3.y*iv3.y + w3.z*iv3.z + w3.w*iv3.w;
            #pragma unroll
            for (int o = 16; o > 0; o >>= 1)
                acc += __shfl_xor_sync(0xffffffffu, acc, o);
            const float hv = acc + b[row];
            const float x2 = hv * hv;
            runs += x2;
            runp *= (1.0f - x2);
        }

        if (lane == 0) { s_ws[w] = runs; s_wp[w] = runp; }
        __syncthreads();
        if (tid == 0) {
            float s = 0.0f, p = 1.0f;
            #pragma unroll
            for (int i = 0; i < 8; i++) { s += s_ws[i]; p *= s_wp[i]; }
            g_sum[bx]  = s;
            g_prod[bx] = p;
        }
    } else {
        // y_out blocks: bx in [512, 516), 32 rows of Wy each, 4 rows per warp.
        const int rb = (bx - 512) * 32 + w * 4;
        #pragma unroll
        for (int i = 0; i < 4; i++) {
            const int row = rb + i;
            const float4* Wr = (const float4*)(Wy + (size_t)row * TOTD);
            float4 w0 = __ldg(Wr + lane +  0);
            float4 w1 = __ldg(Wr + lane + 32);
            float4 w2 = __ldg(Wr + lane + 64);
            float4 w3 = __ldg(Wr + lane + 96);
            float acc = w0.x*iv0.x + w0.y*iv0.y + w0.z*iv0.z + w0.w*iv0.w;
            acc      += w1.x*iv1.x + w1.y*iv1.y + w1.z*iv1.z + w1.w*iv1.w;
            acc      += w2.x*iv2.x + w2.y*iv2.y + w2.z*iv2.z + w2.w*iv2.w;
            acc      += w3.x*iv3.x + w3.y*iv3.y + w3.z*iv3.z + w3.w*iv3.w;
            #pragma unroll
            for (int o = 16; o > 0; o >>= 1)
                acc += __shfl_xor_sync(0xffffffffu, acc, o);
            if (lane == 0) out[HIDD + row] = acc + by[row];
        }
    }
}

__global__ void wavelet_combine_kernel(float* __restrict__ out)
{
    const int t = threadIdx.x;   // 0..255
    if (t >= HIDD) return;
    const float s = g_sum[2 * t] + g_sum[2 * t + 1];
    float a;
    if (t == 0) {
        // first unit: Gaussian scaling fn, product of exp(-0.5 x^2) == exp(-0.5 * sum)
        a = expf(-0.5f * s);
    } else {
        const float p = g_prod[2 * t] * g_prod[2 * t + 1];
        a = p * expf(-0.5f * s);
    }
    out[t] = a;
}

extern "C" void kernel_launch(void* const* d_in, const int* in_sizes, int n_in,
                              void* d_out, int out_size)
{
    const float* h  = (const float*)d_in[0];
    const float* y  = (const float*)d_in[1];
    const float* u  = (const float*)d_in[2];
    const float* W1 = (const float*)d_in[3];
    const float* b1 = (const float*)d_in[4];
    const float* W2 = (const float*)d_in[5];
    const float* b2 = (const float*)d_in[6];
    const float* Wy = (const float*)d_in[7];
    const float* by = (const float*)d_in[8];
    float* out = (float*)d_out;

    wavelet_main_kernel<<<516, 256>>>(h, y, u, W1, b1, W2, b2, Wy, by, out);
    wavelet_combine_kernel<<<1, 256>>>(out);
}

// round 3
// speedup vs baseline: 1.2696x; 1.2696x over previous
#include <cuda_runtime.h>

#define TOTD 512
#define HIDD 256
#define OUTD 128

// Scratch: per-(k,half) partial sum-of-squares and partial product.
__device__ float g_sum[512];
__device__ float g_prod[512];
__device__ unsigned int g_count = 0;   // self-resetting via atomicInc wrap

__global__ void __launch_bounds__(256, 4) wavelet_fused_kernel(
    const float* __restrict__ h, const float* __restrict__ y, const float* __restrict__ u,
    const float* __restrict__ W1, const float* __restrict__ b1,
    const float* __restrict__ W2, const float* __restrict__ b2,
    const float* __restrict__ Wy, const float* __restrict__ by,
    float* __restrict__ out)
{
    __shared__ float4 s_inp[TOTD / 4];
    __shared__ float s_ws[8], s_wp[8];
    __shared__ bool s_last;

    const int tid = threadIdx.x;
    // Build inp = concat(h[256], y[128], u[128]) in shared.
    float* si = (float*)s_inp;
    for (int i = tid; i < TOTD; i += 256) {
        float v;
        if (i < HIDD)             v = h[i];
        else if (i < HIDD + OUTD) v = y[i - HIDD];
        else                      v = u[i - HIDD - OUTD];
        si[i] = v;
    }
    if (tid == 0) s_last = false;
    __syncthreads();

    const int lane = tid & 31;
    const int w    = tid >> 5;   // warp id 0..7
    const int bx   = blockIdx.x;

    // Input slice for this lane, register-resident (reused across all rows).
    const float4 iv0 = s_inp[lane +  0];
    const float4 iv1 = s_inp[lane + 32];
    const float4 iv2 = s_inp[lane + 64];
    const float4 iv3 = s_inp[lane + 96];

    if (bx < 512) {
        // Hidden-unit matvecs: block bx handles k = bx/2, rows [ (bx&1)*256, +256 )
        const int kk   = bx >> 1;      // 0..255
        const int half = bx & 1;
        const float* W;
        const float* b;
        if (kk == 0) { W = W1; b = b1; }
        else {
            W = W2 + (size_t)(kk - 1) * TOTD * TOTD;
            b = b2 + (size_t)(kk - 1) * TOTD;
        }

        float runs = 0.0f;   // sum of x^2
        float runp = 1.0f;   // product of (1 - x^2)
        const int rbase = half * 256 + w * 32;

        // 2 rows per iteration: 8 independent LDG.128 in flight per warp (1 KB)
        #pragma unroll 1
        for (int i = 0; i < 16; i++) {
            const int rowA = rbase + 2 * i;
            const float4* WrA = (const float4*)(W + (size_t)rowA * TOTD);
            const float4* WrB = WrA + (TOTD / 4);
            float4 a0 = __ldcs(WrA + lane +  0);
            float4 a1 = __ldcs(WrA + lane + 32);
            float4 a2 = __ldcs(WrA + lane + 64);
            float4 a3 = __ldcs(WrA + lane + 96);
            float4 c0 = __ldcs(WrB + lane +  0);
            float4 c1 = __ldcs(WrB + lane + 32);
            float4 c2 = __ldcs(WrB + lane + 64);
            float4 c3 = __ldcs(WrB + lane + 96);
            const float bA = b[rowA];
            const float bB = b[rowA + 1];

            float accA = a0.x*iv0.x + a0.y*iv0.y + a0.z*iv0.z + a0.w*iv0.w;
            float accB = c0.x*iv0.x + c0.y*iv0.y + c0.z*iv0.z + c0.w*iv0.w;
            accA      += a1.x*iv1.x + a1.y*iv1.y + a1.z*iv1.z + a1.w*iv1.w;
            accB      += c1.x*iv1.x + c1.y*iv1.y + c1.z*iv1.z + c1.w*iv1.w;
            accA      += a2.x*iv2.x + a2.y*iv2.y + a2.z*iv2.z + a2.w*iv2.w;
            accB      += c2.x*iv2.x + c2.y*iv2.y + c2.z*iv2.z + c2.w*iv2.w;
            accA      += a3.x*iv3.x + a3.y*iv3.y + a3.z*iv3.z + a3.w*iv3.w;
            accB      += c3.x*iv3.x + c3.y*iv3.y + c3.z*iv3.z + c3.w*iv3.w;

            #pragma unroll
            for (int o = 16; o > 0; o >>= 1) {
                accA += __shfl_xor_sync(0xffffffffu, accA, o);
                accB += __shfl_xor_sync(0xffffffffu, accB, o);
            }
            const float hA = accA + bA;
            const float hB = accB + bB;
            const float xA = hA * hA;
            const float xB = hB * hB;
            runs += xA + xB;
            runp *= (1.0f - xA) * (1.0f - xB);
        }

        if (lane == 0) { s_ws[w] = runs; s_wp[w] = runp; }
        __syncthreads();
        if (tid == 0) {
            float s = 0.0f, p = 1.0f;
            #pragma unroll
            for (int i = 0; i < 8; i++) { s += s_ws[i]; p *= s_wp[i]; }
            g_sum[bx]  = s;
            g_prod[bx] = p;
            // Publish, then count arrivals. atomicInc wraps 511 -> 0, so the
            // counter self-resets for the next graph replay.
            __threadfence();
            unsigned int v = atomicInc(&g_count, 511u);
            s_last = (v == 511u);
        }
        __syncthreads();

        if (s_last) {
            // Last-arriving block performs the combine for out[0..255].
            const int t = tid;   // 0..255
            const float s = __ldcg(&g_sum[2 * t]) + __ldcg(&g_sum[2 * t + 1]);
            float a;
            if (t == 0) {
                a = expf(-0.5f * s);   // Gaussian scaling unit
            } else {
                const float p = __ldcg(&g_prod[2 * t]) * __ldcg(&g_prod[2 * t + 1]);
                a = p * expf(-0.5f * s);   // Mexican-hat product
            }
            out[t] = a;
        }
    } else {
        // y_out blocks: bx in [512, 516), 32 rows of Wy each, 4 rows per warp.
        const int rb = (bx - 512) * 32 + w * 4;
        #pragma unroll
        for (int i = 0; i < 4; i += 2) {
            const int rowA = rb + i;
            const float4* WrA = (const float4*)(Wy + (size_t)rowA * TOTD);
            const float4* WrB = WrA + (TOTD / 4);
            float4 a0 = __ldg(WrA + lane +  0);
            float4 a1 = __ldg(WrA + lane + 32);
            float4 a2 = __ldg(WrA + lane + 64);
            float4 a3 = __ldg(WrA + lane + 96);
            float4 c0 = __ldg(WrB + lane +  0);
            float4 c1 = __ldg(WrB + lane + 32);
            float4 c2 = __ldg(WrB + lane + 64);
            float4 c3 = __ldg(WrB + lane + 96);

            float accA = a0.x*iv0.x + a0.y*iv0.y + a0.z*iv0.z + a0.w*iv0.w;
            float accB = c0.x*iv0.x + c0.y*iv0.y + c0.z*iv0.z + c0.w*iv0.w;
            accA      += a1.x*iv1.x + a1.y*iv1.y + a1.z*iv1.z + a1.w*iv1.w;
            accB      += c1.x*iv1.x + c1.y*iv1.y + c1.z*iv1.z + c1.w*iv1.w;
            accA      += a2.x*iv2.x + a2.y*iv2.y + a2.z*iv2.z + a2.w*iv2.w;
            accB      += c2.x*iv2.x + c2.y*iv2.y + c2.z*iv2.z + c2.w*iv2.w;
            accA      += a3.x*iv3.x + a3.y*iv3.y + a3.z*iv3.z + a3.w*iv3.w;
            accB      += c3.x*iv3.x + c3.y*iv3.y + c3.z*iv3.z + c3.w*iv3.w;

            #pragma unroll
            for (int o = 16; o > 0; o >>= 1) {
                accA += __shfl_xor_sync(0xffffffffu, accA, o);
                accB += __shfl_xor_sync(0xffffffffu, accB, o);
            }
            if (lane == 0) {
                out[HIDD + rowA]     = accA + by[rowA];
                out[HIDD + rowA + 1] = accB + by[rowA + 1];
            }
        }
    }
}

extern "C" void kernel_launch(void* const* d_in, const int* in_sizes, int n_in,
                              void* d_out, int out_size)
{
    const float* h  = (const float*)d_in[0];
    const float* y  = (const float*)d_in[1];
    const float* u  = (const float*)d_in[2];
    const float* W1 = (const float*)d_in[3];
    const float* b1 = (const float*)d_in[4];
    const float* W2 = (const float*)d_in[5];
    const float* b2 = (const float*)d_in[6];
    const float* Wy = (const float*)d_in[7];
    const float* by = (const float*)d_in[8];
    float* out = (float*)d_out;

    wavelet_fused_kernel<<<516, 256>>>(h, y, u, W1, b1, W2, b2, Wy, by, out);
}